// round 2
// baseline (speedup 1.0000x reference)
#include <cuda_runtime.h>

#define BATCH  16
#define GROUPS 16
#define NCH    64
#define EPSV   1e-5f

// Global scratch (allocation-free: __device__ arrays)
__device__ float  g_sum[BATCH * GROUPS];
__device__ float  g_ssq[BATCH * GROUPS];
__device__ float4 g_A4[BATCH * 16];   // per (batch, channel) scale, as float4 quads
__device__ float4 g_B4[BATCH * 16];   // per (batch, channel) shift

__global__ void ogn_zero_kernel() {
    int t = threadIdx.x;
    if (t < BATCH * GROUPS) { g_sum[t] = 0.f; g_ssq[t] = 0.f; }
}

// Pass 1: per-(batch, group) sum and sum-of-squares.
// Layout: 256 threads = 16 group-lanes (float4 = one group's 4 channels)
//         x 16 row-lanes. Each block owns a contiguous row chunk so the
//         sorted batch_id changes at most a couple times per thread.
__global__ void ogn_pass1_kernel(const float4* __restrict__ data4,
                                 const int* __restrict__ batch_id,
                                 int nrows) {
    __shared__ float s_sum[BATCH][GROUPS];
    __shared__ float s_ssq[BATCH][GROUPS];
    int t = threadIdx.x;
    if (t < BATCH * GROUPS) { s_sum[t >> 4][t & 15] = 0.f; s_ssq[t >> 4][t & 15] = 0.f; }
    __syncthreads();

    const int g  = t & 15;        // group lane (float4 index within row)
    const int rl = t >> 4;        // row lane
    int chunk = (nrows + gridDim.x - 1) / gridDim.x;
    int r0 = blockIdx.x * chunk;
    int r1 = min(r0 + chunk, nrows);

    float gsum = 0.f, gssq = 0.f;
    int cur = -1;
    for (int row = r0 + rl; row < r1; row += 16) {
        int b = __ldg(&batch_id[row]);     // broadcast across the 16 group lanes
        if (b != cur) {
            if (cur >= 0) {
                atomicAdd(&s_sum[cur][g], gsum);
                atomicAdd(&s_ssq[cur][g], gssq);
            }
            cur = b; gsum = 0.f; gssq = 0.f;
        }
        float4 v = data4[(long)row * 16 + g];
        gsum += (v.x + v.y) + (v.z + v.w);
        gssq += v.x * v.x + v.y * v.y + v.z * v.z + v.w * v.w;
    }
    if (cur >= 0) {
        atomicAdd(&s_sum[cur][g], gsum);
        atomicAdd(&s_ssq[cur][g], gssq);
    }
    __syncthreads();

    if (t < BATCH * GROUPS) {
        float s = s_sum[t >> 4][t & 15];
        float q = s_ssq[t >> 4][t & 15];
        if (s != 0.f || q != 0.f) {       // skip batches this block never saw
            atomicAdd(&g_sum[t], s);
            atomicAdd(&g_ssq[t], q);
        }
    }
}

// Stats: per-batch counts via binary search on sorted batch_id, then fold
// mean/inv_std/weights/bias into per-(batch,channel) affine A, B.
__global__ void ogn_stats_kernel(const int* __restrict__ batch_id, int nrows,
                                 const float* __restrict__ weights,
                                 const float* __restrict__ bias) {
    __shared__ int   s_start[BATCH + 1];
    __shared__ float s_mean[BATCH][GROUPS];
    __shared__ float s_istd[BATCH][GROUPS];
    int t = threadIdx.x;  // 1024 threads

    if (t <= BATCH) {
        if (t == BATCH) {
            s_start[t] = nrows;
        } else {
            int lo = 0, hi = nrows;  // first idx with batch_id[idx] >= t
            while (lo < hi) {
                int mid = (lo + hi) >> 1;
                if (__ldg(&batch_id[mid]) < t) lo = mid + 1; else hi = mid;
            }
            s_start[t] = lo;
        }
    }
    __syncthreads();

    if (t < BATCH * GROUPS) {
        int b = t >> 4;
        float n = (float)(s_start[b + 1] - s_start[b]);
        float inv_count = 1.f / (n * 4.f + EPSV);
        float s = g_sum[t], q = g_ssq[t];
        float m = s * inv_count;
        float var = (q - 2.f * m * s + 4.f * n * m * m) * inv_count;
        s_mean[b][t & 15] = m;
        s_istd[b][t & 15] = rsqrtf(var + EPSV);
    }
    __syncthreads();

    {   // 1024 = 16 batches x 64 channels
        int b = t >> 6, c = t & 63, g = c >> 2;
        float w  = weights[c];
        float bi = bias[c];
        float A  = s_istd[b][g] * w;
        ((float*)g_A4)[t] = A;
        ((float*)g_B4)[t] = bi - s_mean[b][g] * A;
    }
}

// Pass 2: out = x * A[b][c] + B[b][c], pure float4 streaming.
__global__ void ogn_pass2_kernel(const float4* __restrict__ data4,
                                 const int* __restrict__ batch_id,
                                 float4* __restrict__ out4,
                                 long n4) {
    __shared__ float4 sA[BATCH][16];
    __shared__ float4 sB[BATCH][16];
    for (int i = threadIdx.x; i < BATCH * 16; i += blockDim.x) {
        sA[i >> 4][i & 15] = g_A4[i];
        sB[i >> 4][i & 15] = g_B4[i];
    }
    __syncthreads();

    long stride = (long)gridDim.x * blockDim.x;
    for (long idx = (long)blockIdx.x * blockDim.x + threadIdx.x; idx < n4; idx += stride) {
        int row = (int)(idx >> 4);
        int q   = (int)(idx & 15);
        int b   = __ldg(&batch_id[row]);   // broadcast across the row's 16 quads
        float4 v  = data4[idx];
        float4 a  = sA[b][q];
        float4 bb = sB[b][q];
        float4 o;
        o.x = fmaf(v.x, a.x, bb.x);
        o.y = fmaf(v.y, a.y, bb.y);
        o.z = fmaf(v.z, a.z, bb.z);
        o.w = fmaf(v.w, a.w, bb.w);
        out4[idx] = o;
    }
}

extern "C" void kernel_launch(void* const* d_in, const int* in_sizes, int n_in,
                              void* d_out, int out_size) {
    const float* data     = (const float*)d_in[0];
    const int*   batch_id = (const int*)d_in[1];
    const float* weights  = (const float*)d_in[2];
    const float* bias     = (const float*)d_in[3];
    float*       out      = (float*)d_out;
    const int    nrows    = in_sizes[1];          // batch_id element count = N

    ogn_zero_kernel<<<1, 256>>>();
    ogn_pass1_kernel<<<1024, 256>>>((const float4*)data, batch_id, nrows);
    ogn_stats_kernel<<<1, 1024>>>(batch_id, nrows, weights, bias);
    ogn_pass2_kernel<<<2048, 256>>>((const float4*)data, batch_id,
                                    (float4*)out, (long)nrows * 16);
}